// round 5
// baseline (speedup 1.0000x reference)
#include <cuda_runtime.h>
#include <math.h>
#include <stdint.h>

#define D_MODEL 256
#define NH 8
#define NL 4
#define NP 4
#define DHEAD 32
#define BATCH 2
#define MAX_M 40960   // >= BATCH * Lq = 39894

// Scratch (static device globals -- no allocation at runtime)
__device__ float g_value[(size_t)MAX_M * D_MODEL];   // (N,H,Lv,Dh)
__device__ float g_off  [(size_t)MAX_M * D_MODEL];   // (N,Lq,H,L,P,2)
__device__ float g_attn [(size_t)MAX_M * (NH*NL*NP)];// logits (N,Lq,H,16)
__device__ float g_acc  [(size_t)MAX_M * D_MODEL];   // (N,Lq,H,Dh)
__device__ float g_Wqk  [384 * 256];                 // W_samp ++ W_attn
__device__ float g_bqk  [384];

// ---------------------------------------------------------------------------
// TF32 mma.sync GEMM: C[M,Ncols] = A[M,256] @ W[Ncols,256]^T + bias
// CTA tile 128x128, 4 warps x (64x64) warp tile, m16n8k8 tf32, double-buffered.
// EPI 0: row-major (stride 256). EPI 1: value remap. EPI 2: off/attn split.
// ---------------------------------------------------------------------------
#define BM 128
#define BN 128
#define BKK 16
#define PAD 8

__device__ __forceinline__ float to_tf32(float x) {
    uint32_t u;
    asm("cvt.rna.tf32.f32 %0, %1;" : "=r"(u) : "f"(x));
    return __uint_as_float(u);
}

__device__ __forceinline__ void mma_tf32(float* c, const uint32_t* a, const uint32_t* b) {
    asm volatile(
        "mma.sync.aligned.m16n8k8.row.col.f32.tf32.tf32.f32 "
        "{%0,%1,%2,%3}, {%4,%5,%6,%7}, {%8,%9}, {%0,%1,%2,%3};"
        : "+f"(c[0]), "+f"(c[1]), "+f"(c[2]), "+f"(c[3])
        : "r"(a[0]), "r"(a[1]), "r"(a[2]), "r"(a[3]), "r"(b[0]), "r"(b[1]));
}

template<int EPI>
__global__ __launch_bounds__(128)
void tgemm_nt(const float* __restrict__ A, const float* __restrict__ W,
              const float* __restrict__ bias, float* __restrict__ C0,
              float* __restrict__ C1, int M, int Lv)
{
    __shared__ float As[2][BKK][BM + PAD];
    __shared__ float Ws[2][BKK][BN + PAD];

    const int tid  = threadIdx.x;
    const int brow = blockIdx.x * BM;
    const int bcol = blockIdx.y * BN;
    const int K = 256;

    const int warp = tid >> 5;
    const int lane = tid & 31;
    const int wm   = (warp & 1) * 64;     // warp M offset
    const int wn   = (warp >> 1) * 64;    // warp N offset
    const int lr   = lane >> 2;           // 0..7
    const int lc   = lane & 3;            // 0..3

    float4 pa[4], pw[4];   // each thread stages one full 16-float row of A and W

    const int grA = brow + tid;
    const int grW = bcol + tid;

    // prefetch tile 0
#pragma unroll
    for (int j = 0; j < 4; j++) {
        pa[j] = (grA < M) ? *reinterpret_cast<const float4*>(A + (size_t)grA * K + j * 4)
                          : make_float4(0.f, 0.f, 0.f, 0.f);
        pw[j] = *reinterpret_cast<const float4*>(W + (size_t)grW * K + j * 4);
    }
#pragma unroll
    for (int j = 0; j < 4; j++) {
        As[0][j * 4 + 0][tid] = to_tf32(pa[j].x); As[0][j * 4 + 1][tid] = to_tf32(pa[j].y);
        As[0][j * 4 + 2][tid] = to_tf32(pa[j].z); As[0][j * 4 + 3][tid] = to_tf32(pa[j].w);
        Ws[0][j * 4 + 0][tid] = to_tf32(pw[j].x); Ws[0][j * 4 + 1][tid] = to_tf32(pw[j].y);
        Ws[0][j * 4 + 2][tid] = to_tf32(pw[j].z); Ws[0][j * 4 + 3][tid] = to_tf32(pw[j].w);
    }
    __syncthreads();

    float acc[4][8][4];
#pragma unroll
    for (int mt = 0; mt < 4; mt++)
#pragma unroll
        for (int nt = 0; nt < 8; nt++)
#pragma unroll
            for (int r = 0; r < 4; r++) acc[mt][nt][r] = 0.f;

    const int nk = K / BKK;
    for (int t = 0; t < nk; t++) {
        const int cur = t & 1;
        if (t + 1 < nk) {
            const int kt = (t + 1) * BKK;
#pragma unroll
            for (int j = 0; j < 4; j++) {
                pa[j] = (grA < M) ? *reinterpret_cast<const float4*>(A + (size_t)grA * K + kt + j * 4)
                                  : make_float4(0.f, 0.f, 0.f, 0.f);
                pw[j] = *reinterpret_cast<const float4*>(W + (size_t)grW * K + kt + j * 4);
            }
        }

#pragma unroll
        for (int ks = 0; ks < 2; ks++) {
            const int kb = ks * 8;
            uint32_t af[4][4], bf[8][2];
#pragma unroll
            for (int mt = 0; mt < 4; mt++) {
                const int m0 = wm + mt * 16;
                af[mt][0] = __float_as_uint(As[cur][kb + lc    ][m0 + lr    ]);
                af[mt][1] = __float_as_uint(As[cur][kb + lc    ][m0 + lr + 8]);
                af[mt][2] = __float_as_uint(As[cur][kb + lc + 4][m0 + lr    ]);
                af[mt][3] = __float_as_uint(As[cur][kb + lc + 4][m0 + lr + 8]);
            }
#pragma unroll
            for (int nt = 0; nt < 8; nt++) {
                const int n0 = wn + nt * 8;
                bf[nt][0] = __float_as_uint(Ws[cur][kb + lc    ][n0 + lr]);
                bf[nt][1] = __float_as_uint(Ws[cur][kb + lc + 4][n0 + lr]);
            }
#pragma unroll
            for (int mt = 0; mt < 4; mt++)
#pragma unroll
                for (int nt = 0; nt < 8; nt++)
                    mma_tf32(acc[mt][nt], af[mt], bf[nt]);
        }

        if (t + 1 < nk) {
            const int nxt = cur ^ 1;
#pragma unroll
            for (int j = 0; j < 4; j++) {
                As[nxt][j * 4 + 0][tid] = to_tf32(pa[j].x); As[nxt][j * 4 + 1][tid] = to_tf32(pa[j].y);
                As[nxt][j * 4 + 2][tid] = to_tf32(pa[j].z); As[nxt][j * 4 + 3][tid] = to_tf32(pa[j].w);
                Ws[nxt][j * 4 + 0][tid] = to_tf32(pw[j].x); Ws[nxt][j * 4 + 1][tid] = to_tf32(pw[j].y);
                Ws[nxt][j * 4 + 2][tid] = to_tf32(pw[j].z); Ws[nxt][j * 4 + 3][tid] = to_tf32(pw[j].w);
            }
        }
        __syncthreads();
    }

    // Epilogue: mma tile rows {lr, lr+8}, cols {2*lc, 2*lc+1}
#pragma unroll
    for (int mt = 0; mt < 4; mt++) {
#pragma unroll
        for (int nt = 0; nt < 8; nt++) {
            const int c0 = bcol + wn + nt * 8 + lc * 2;
            const float b0 = __ldg(bias + c0);
            const float b1 = __ldg(bias + c0 + 1);
#pragma unroll
            for (int rr = 0; rr < 2; rr++) {
                const int r = brow + wm + mt * 16 + lr + rr * 8;
                if (r >= M) continue;
                const float v0 = acc[mt][nt][rr * 2 + 0] + b0;
                const float v1 = acc[mt][nt][rr * 2 + 1] + b1;
                if (EPI == 0) {
                    *reinterpret_cast<float2*>(C0 + (size_t)r * 256 + c0) = make_float2(v0, v1);
                } else if (EPI == 1) {
                    const int nb = r / Lv, l = r - nb * Lv;
                    const int h = c0 >> 5, dh = c0 & 31;  // c0 even -> pair stays in one head
                    float* p = C0 + ((((size_t)(nb * NH + h)) * Lv) + l) * DHEAD + dh;
                    *reinterpret_cast<float2*>(p) = make_float2(v0, v1);
                } else {
                    if (c0 < 256)
                        *reinterpret_cast<float2*>(C0 + (size_t)r * 256 + c0) = make_float2(v0, v1);
                    else
                        *reinterpret_cast<float2*>(C1 + (size_t)r * 128 + (c0 - 256)) = make_float2(v0, v1);
                }
            }
        }
    }
}

// ---------------------------------------------------------------------------
// Pack W_samp ++ W_attn into one 384x256 weight (shared-A GEMM merge)
// ---------------------------------------------------------------------------
__global__ void pack_qk(const float* __restrict__ Ws, const float* __restrict__ bs,
                        const float* __restrict__ Wa, const float* __restrict__ ba)
{
    const int i = blockIdx.x * 256 + threadIdx.x;
    if (i < 65536)       g_Wqk[i] = Ws[i];
    else if (i < 98304)  g_Wqk[i] = Wa[i - 65536];
    if (i < 256)         g_bqk[i] = bs[i];
    else if (i < 384)    g_bqk[i] = ba[i - 256];
}

// ---------------------------------------------------------------------------
// Sampling + softmax, two-phase (at LDG-issue floor; unchanged)
// ---------------------------------------------------------------------------
__global__ __launch_bounds__(256)
void msda_sample(const float* __restrict__ ref,
                 const int* __restrict__ shapes,
                 const int* __restrict__ lstart,
                 int Lq, int total)
{
    __shared__ int   s_idx[16][16][4];
    __shared__ float s_w  [16][16][4];
    __shared__ int   s_vbase[16];

    const int tid = threadIdx.x;

    // ---------------- Phase 1 ----------------
    {
        const int u  = tid >> 4;
        const int pt = tid & 15;
        const int gu = blockIdx.x * 16 + u;
        const bool act = gu < total;

        const int h  = gu & (NH - 1);
        const int mq = gu >> 3;                    // n*Lq + q

        float logit = act ? __ldg(g_attn + (size_t)gu * 16 + pt) : 0.f;
        float mx = logit;
#pragma unroll
        for (int s = 8; s > 0; s >>= 1) mx = fmaxf(mx, __shfl_xor_sync(0xffffffffu, mx, s));
        float e = __expf(logit - mx);
        float sum = e;
#pragma unroll
        for (int s = 8; s > 0; s >>= 1) sum += __shfl_xor_sync(0xffffffffu, sum, s);
        const float aw = e / sum;

        if (act) {
            const int lvl = pt >> 2;
            const int Hl = __ldg(shapes + lvl * 2 + 0);
            const int Wl = __ldg(shapes + lvl * 2 + 1);
            const int st = __ldg(lstart + lvl);

            const float rx = __ldg(ref + (size_t)mq * (NL * 2) + lvl * 2 + 0);
            const float ry = __ldg(ref + (size_t)mq * (NL * 2) + lvl * 2 + 1);
            const float ox = __ldg(g_off + (size_t)gu * 32 + 2 * pt + 0);
            const float oy = __ldg(g_off + (size_t)gu * 32 + 2 * pt + 1);

            const float x = fmaf(rx, (float)Wl, ox) - 0.5f;
            const float y = fmaf(ry, (float)Hl, oy) - 0.5f;
            const float xf = floorf(x), yf = floorf(y);
            const float lx = x - xf, ly = y - yf;
            const int x0 = (int)xf, y0 = (int)yf;
            const int x1 = x0 + 1,  y1 = y0 + 1;

            const float vx0 = (x0 >= 0 && x0 < Wl) ? 1.f : 0.f;
            const float vx1 = (x1 >= 0 && x1 < Wl) ? 1.f : 0.f;
            const float vy0 = (y0 >= 0 && y0 < Hl) ? 1.f : 0.f;
            const float vy1 = (y1 >= 0 && y1 < Hl) ? 1.f : 0.f;

            const int x0c = min(max(x0, 0), Wl - 1);
            const int x1c = min(max(x1, 0), Wl - 1);
            const int y0c = min(max(y0, 0), Hl - 1);
            const int y1c = min(max(y1, 0), Hl - 1);

            const int r0 = (st + y0c * Wl) * DHEAD;
            const int r1 = (st + y1c * Wl) * DHEAD;
            s_idx[u][pt][0] = r0 + x0c * DHEAD;
            s_idx[u][pt][1] = r0 + x1c * DHEAD;
            s_idx[u][pt][2] = r1 + x0c * DHEAD;
            s_idx[u][pt][3] = r1 + x1c * DHEAD;

            s_w[u][pt][0] = aw * (1.f - lx) * (1.f - ly) * vx0 * vy0;
            s_w[u][pt][1] = aw * lx * (1.f - ly) * vx1 * vy0;
            s_w[u][pt][2] = aw * (1.f - lx) * ly * vx0 * vy1;
            s_w[u][pt][3] = aw * lx * ly * vx1 * vy1;

            if (pt == 0) {
                const int n = mq / Lq;
                s_vbase[u] = ((n * NH + h) * Lq) * DHEAD;
            }
        }
    }
    __syncthreads();

    // ---------------- Phase 2 ----------------
    {
        const int warp = tid >> 5;
        const int lane = tid & 31;
#pragma unroll
        for (int uu = 0; uu < 2; uu++) {
            const int u  = warp * 2 + uu;
            const int gu = blockIdx.x * 16 + u;
            if (gu >= total) continue;

            const float* bp = g_value + s_vbase[u] + lane;
            float acc = 0.f;
#pragma unroll
            for (int pt = 0; pt < 16; pt++) {
                const int4   id = *reinterpret_cast<const int4*>(s_idx[u][pt]);
                const float4 w  = *reinterpret_cast<const float4*>(s_w[u][pt]);
                acc = fmaf(w.x, __ldg(bp + id.x), acc);
                acc = fmaf(w.y, __ldg(bp + id.y), acc);
                acc = fmaf(w.z, __ldg(bp + id.z), acc);
                acc = fmaf(w.w, __ldg(bp + id.w), acc);
            }
            g_acc[(size_t)gu * DHEAD + lane] = acc;
        }
    }
}

// ---------------------------------------------------------------------------
// Launch
// ---------------------------------------------------------------------------
extern "C" void kernel_launch(void* const* d_in, const int* in_sizes, int n_in,
                              void* d_out, int out_size)
{
    const float* query  = (const float*)d_in[0];
    const float* refp   = (const float*)d_in[1];
    const float* xin    = (const float*)d_in[2];
    const int*   shapes = (const int*)  d_in[3];
    const int*   lstart = (const int*)  d_in[4];
    const float* W_samp = (const float*)d_in[5];
    const float* b_samp = (const float*)d_in[6];
    const float* W_attn = (const float*)d_in[7];
    const float* b_attn = (const float*)d_in[8];
    const float* W_val  = (const float*)d_in[9];
    const float* b_val  = (const float*)d_in[10];
    const float* W_out  = (const float*)d_in[11];
    const float* b_out  = (const float*)d_in[12];
    float* out = (float*)d_out;

    const int Lq = in_sizes[0] / (BATCH * D_MODEL);
    const int M  = BATCH * Lq;

    void *pv, *po, *pa, *pc, *pwqk, *pbqk;
    cudaGetSymbolAddress(&pv, g_value);
    cudaGetSymbolAddress(&po, g_off);
    cudaGetSymbolAddress(&pa, g_attn);
    cudaGetSymbolAddress(&pc, g_acc);
    cudaGetSymbolAddress(&pwqk, g_Wqk);
    cudaGetSymbolAddress(&pbqk, g_bqk);

    const int gx = (M + BM - 1) / BM;
    dim3 gblk(128);
    dim3 blk(256);

    // 0) pack merged qk weights
    pack_qk<<<384, blk>>>(W_samp, b_samp, W_attn, b_attn);
    // 1) value projection (+ layout remap to (N,H,Lv,Dh))
    tgemm_nt<1><<<dim3(gx, 2), gblk>>>(xin, W_val, b_val, (float*)pv, nullptr, M, Lq);
    // 2+3) merged sampling-offset + attention-logit projection (N = 384)
    tgemm_nt<2><<<dim3(gx, 3), gblk>>>(query, (const float*)pwqk, (const float*)pbqk,
                                       (float*)po, (float*)pa, M, Lq);
    // 4) softmax + deformable sampling
    {
        const int total = M * NH;
        const int nblk  = (total + 15) / 16;
        msda_sample<<<nblk, blk>>>(refp, shapes, lstart, Lq, total);
    }
    // 5) output projection
    tgemm_nt<0><<<dim3(gx, 2), gblk>>>((const float*)pc, W_out, b_out, out, nullptr, M, Lq);
}

// round 6
// speedup vs baseline: 1.3827x; 1.3827x over previous
#include <cuda_runtime.h>
#include <cuda_fp16.h>
#include <math.h>
#include <stdint.h>

#define D_MODEL 256
#define NH 8
#define NL 4
#define NP 4
#define DHEAD 32
#define BATCH 2
#define MAX_M 40960   // >= BATCH * Lq = 39894

// Scratch (static device globals -- no allocation at runtime)
__device__ float g_value[(size_t)MAX_M * D_MODEL];   // (N,H,Lv,Dh)
__device__ float g_off  [(size_t)MAX_M * D_MODEL];   // (N,Lq,H,L,P,2)
__device__ float g_attn [(size_t)MAX_M * (NH*NL*NP)];// logits (N,Lq,H,16)
__device__ float g_acc  [(size_t)MAX_M * D_MODEL];   // (N,Lq,H,Dh)
__device__ float g_Wqk  [384 * 256];                 // W_samp ++ W_attn
__device__ float g_bqk  [384];

// ---------------------------------------------------------------------------
// FP16 mma.sync GEMM (fp32 accum): C[M,Ncols] = A[M,256] @ W[Ncols,256]^T + b
// CTA tile 128x128, 8 warps x (64x32) warp tile, m16n8k16, double-buffered.
// EPI 0: row-major (stride 256). EPI 1: value remap. EPI 2: off/attn split.
// ---------------------------------------------------------------------------
#define BM 128
#define BN 128
#define BKK 32
#define PADH 8

__device__ __forceinline__ void mma_f16(float* c, const uint32_t* a, const uint32_t* b) {
    asm volatile(
        "mma.sync.aligned.m16n8k16.row.col.f32.f16.f16.f32 "
        "{%0,%1,%2,%3}, {%4,%5,%6,%7}, {%8,%9}, {%0,%1,%2,%3};"
        : "+f"(c[0]), "+f"(c[1]), "+f"(c[2]), "+f"(c[3])
        : "r"(a[0]), "r"(a[1]), "r"(a[2]), "r"(a[3]), "r"(b[0]), "r"(b[1]));
}

template<int EPI>
__global__ __launch_bounds__(256)
void hgemm_nt(const float* __restrict__ A, const float* __restrict__ W,
              const float* __restrict__ bias, float* __restrict__ C0,
              float* __restrict__ C1, int M, int Lv)
{
    __shared__ alignas(16) __half As[2][BM][BKK + PADH];
    __shared__ alignas(16) __half Bs[2][BN][BKK + PADH];

    const int tid  = threadIdx.x;
    const int brow = blockIdx.x * BM;
    const int bcol = blockIdx.y * BN;
    const int K = 256;

    const int warp = tid >> 5;
    const int lane = tid & 31;
    const int wm   = (warp & 1) * 64;     // warp M offset
    const int wn   = (warp >> 1) * 32;    // warp N offset
    const int lr   = lane >> 2;           // 0..7
    const int lc   = lane & 3;            // 0..3

    const int ldRow = tid >> 1;           // 0..127
    const int ldSeg = (tid & 1) * 16;     // 0 or 16 (floats)
    const int grA   = brow + ldRow;
    const int grW   = bcol + ldRow;

    float4 pa[4], pw[4];

    // prefetch tile 0
#pragma unroll
    for (int j = 0; j < 4; j++) {
        pa[j] = (grA < M) ? *reinterpret_cast<const float4*>(A + (size_t)grA * K + ldSeg + j * 4)
                          : make_float4(0.f, 0.f, 0.f, 0.f);
        pw[j] = *reinterpret_cast<const float4*>(W + (size_t)grW * K + ldSeg + j * 4);
    }
#pragma unroll
    for (int j = 0; j < 4; j++) {
        *reinterpret_cast<__half2*>(&As[0][ldRow][ldSeg + j * 4    ]) = __float22half2_rn(make_float2(pa[j].x, pa[j].y));
        *reinterpret_cast<__half2*>(&As[0][ldRow][ldSeg + j * 4 + 2]) = __float22half2_rn(make_float2(pa[j].z, pa[j].w));
        *reinterpret_cast<__half2*>(&Bs[0][ldRow][ldSeg + j * 4    ]) = __float22half2_rn(make_float2(pw[j].x, pw[j].y));
        *reinterpret_cast<__half2*>(&Bs[0][ldRow][ldSeg + j * 4 + 2]) = __float22half2_rn(make_float2(pw[j].z, pw[j].w));
    }
    __syncthreads();

    float acc[4][4][4];
#pragma unroll
    for (int mt = 0; mt < 4; mt++)
#pragma unroll
        for (int nt = 0; nt < 4; nt++)
#pragma unroll
            for (int r = 0; r < 4; r++) acc[mt][nt][r] = 0.f;

    const int nk = K / BKK;               // 8
    for (int t = 0; t < nk; t++) {
        const int cur = t & 1;
        if (t + 1 < nk) {
            const int kt = (t + 1) * BKK;
#pragma unroll
            for (int j = 0; j < 4; j++) {
                pa[j] = (grA < M) ? *reinterpret_cast<const float4*>(A + (size_t)grA * K + kt + ldSeg + j * 4)
                                  : make_float4(0.f, 0.f, 0.f, 0.f);
                pw[j] = *reinterpret_cast<const float4*>(W + (size_t)grW * K + kt + ldSeg + j * 4);
            }
        }

#pragma unroll
        for (int ks = 0; ks < 2; ks++) {
            const int kb = ks * 16;
            uint32_t af[4][4], bf[4][2];
#pragma unroll
            for (int mt = 0; mt < 4; mt++) {
                const int m0 = wm + mt * 16;
                af[mt][0] = *reinterpret_cast<const uint32_t*>(&As[cur][m0 + lr    ][kb + lc * 2    ]);
                af[mt][1] = *reinterpret_cast<const uint32_t*>(&As[cur][m0 + lr + 8][kb + lc * 2    ]);
                af[mt][2] = *reinterpret_cast<const uint32_t*>(&As[cur][m0 + lr    ][kb + lc * 2 + 8]);
                af[mt][3] = *reinterpret_cast<const uint32_t*>(&As[cur][m0 + lr + 8][kb + lc * 2 + 8]);
            }
#pragma unroll
            for (int nt = 0; nt < 4; nt++) {
                const int n0 = wn + nt * 8;
                bf[nt][0] = *reinterpret_cast<const uint32_t*>(&Bs[cur][n0 + lr][kb + lc * 2    ]);
                bf[nt][1] = *reinterpret_cast<const uint32_t*>(&Bs[cur][n0 + lr][kb + lc * 2 + 8]);
            }
#pragma unroll
            for (int mt = 0; mt < 4; mt++)
#pragma unroll
                for (int nt = 0; nt < 4; nt++)
                    mma_f16(acc[mt][nt], af[mt], bf[nt]);
        }

        if (t + 1 < nk) {
            const int nxt = cur ^ 1;
#pragma unroll
            for (int j = 0; j < 4; j++) {
                *reinterpret_cast<__half2*>(&As[nxt][ldRow][ldSeg + j * 4    ]) = __float22half2_rn(make_float2(pa[j].x, pa[j].y));
                *reinterpret_cast<__half2*>(&As[nxt][ldRow][ldSeg + j * 4 + 2]) = __float22half2_rn(make_float2(pa[j].z, pa[j].w));
                *reinterpret_cast<__half2*>(&Bs[nxt][ldRow][ldSeg + j * 4    ]) = __float22half2_rn(make_float2(pw[j].x, pw[j].y));
                *reinterpret_cast<__half2*>(&Bs[nxt][ldRow][ldSeg + j * 4 + 2]) = __float22half2_rn(make_float2(pw[j].z, pw[j].w));
            }
        }
        __syncthreads();
    }

    // Epilogue: mma tile rows {lr, lr+8}, cols {2*lc, 2*lc+1}
#pragma unroll
    for (int mt = 0; mt < 4; mt++) {
#pragma unroll
        for (int nt = 0; nt < 4; nt++) {
            const int c0 = bcol + wn + nt * 8 + lc * 2;
            const float b0 = __ldg(bias + c0);
            const float b1 = __ldg(bias + c0 + 1);
#pragma unroll
            for (int rr = 0; rr < 2; rr++) {
                const int r = brow + wm + mt * 16 + lr + rr * 8;
                if (r >= M) continue;
                const float v0 = acc[mt][nt][rr * 2 + 0] + b0;
                const float v1 = acc[mt][nt][rr * 2 + 1] + b1;
                if (EPI == 0) {
                    *reinterpret_cast<float2*>(C0 + (size_t)r * 256 + c0) = make_float2(v0, v1);
                } else if (EPI == 1) {
                    const int nb = r / Lv, l = r - nb * Lv;
                    const int h = c0 >> 5, dh = c0 & 31;  // c0 even -> pair stays in one head
                    float* p = C0 + ((((size_t)(nb * NH + h)) * Lv) + l) * DHEAD + dh;
                    *reinterpret_cast<float2*>(p) = make_float2(v0, v1);
                } else {
                    if (c0 < 256)
                        *reinterpret_cast<float2*>(C0 + (size_t)r * 256 + c0) = make_float2(v0, v1);
                    else
                        *reinterpret_cast<float2*>(C1 + (size_t)r * 128 + (c0 - 256)) = make_float2(v0, v1);
                }
            }
        }
    }
}

// ---------------------------------------------------------------------------
// Pack W_samp ++ W_attn into one 384x256 weight (shared-A GEMM merge)
// ---------------------------------------------------------------------------
__global__ void pack_qk(const float* __restrict__ Ws, const float* __restrict__ bs,
                        const float* __restrict__ Wa, const float* __restrict__ ba)
{
    const int i = blockIdx.x * 256 + threadIdx.x;
    if (i < 65536)       g_Wqk[i] = Ws[i];
    else if (i < 98304)  g_Wqk[i] = Wa[i - 65536];
    if (i < 256)         g_bqk[i] = bs[i];
    else if (i < 384)    g_bqk[i] = ba[i - 256];
}

// ---------------------------------------------------------------------------
// Sampling + softmax, two-phase (at L1 wavefront floor; unchanged)
// ---------------------------------------------------------------------------
__global__ __launch_bounds__(256)
void msda_sample(const float* __restrict__ ref,
                 const int* __restrict__ shapes,
                 const int* __restrict__ lstart,
                 int Lq, int total)
{
    __shared__ int   s_idx[16][16][4];
    __shared__ float s_w  [16][16][4];
    __shared__ int   s_vbase[16];

    const int tid = threadIdx.x;

    // ---------------- Phase 1 ----------------
    {
        const int u  = tid >> 4;
        const int pt = tid & 15;
        const int gu = blockIdx.x * 16 + u;
        const bool act = gu < total;

        const int h  = gu & (NH - 1);
        const int mq = gu >> 3;                    // n*Lq + q

        float logit = act ? __ldg(g_attn + (size_t)gu * 16 + pt) : 0.f;
        float mx = logit;
#pragma unroll
        for (int s = 8; s > 0; s >>= 1) mx = fmaxf(mx, __shfl_xor_sync(0xffffffffu, mx, s));
        float e = __expf(logit - mx);
        float sum = e;
#pragma unroll
        for (int s = 8; s > 0; s >>= 1) sum += __shfl_xor_sync(0xffffffffu, sum, s);
        const float aw = e / sum;

        if (act) {
            const int lvl = pt >> 2;
            const int Hl = __ldg(shapes + lvl * 2 + 0);
            const int Wl = __ldg(shapes + lvl * 2 + 1);
            const int st = __ldg(lstart + lvl);

            const float rx = __ldg(ref + (size_t)mq * (NL * 2) + lvl * 2 + 0);
            const float ry = __ldg(ref + (size_t)mq * (NL * 2) + lvl * 2 + 1);
            const float ox = __ldg(g_off + (size_t)gu * 32 + 2 * pt + 0);
            const float oy = __ldg(g_off + (size_t)gu * 32 + 2 * pt + 1);

            const float x = fmaf(rx, (float)Wl, ox) - 0.5f;
            const float y = fmaf(ry, (float)Hl, oy) - 0.5f;
            const float xf = floorf(x), yf = floorf(y);
            const float lx = x - xf, ly = y - yf;
            const int x0 = (int)xf, y0 = (int)yf;
            const int x1 = x0 + 1,  y1 = y0 + 1;

            const float vx0 = (x0 >= 0 && x0 < Wl) ? 1.f : 0.f;
            const float vx1 = (x1 >= 0 && x1 < Wl) ? 1.f : 0.f;
            const float vy0 = (y0 >= 0 && y0 < Hl) ? 1.f : 0.f;
            const float vy1 = (y1 >= 0 && y1 < Hl) ? 1.f : 0.f;

            const int x0c = min(max(x0, 0), Wl - 1);
            const int x1c = min(max(x1, 0), Wl - 1);
            const int y0c = min(max(y0, 0), Hl - 1);
            const int y1c = min(max(y1, 0), Hl - 1);

            const int r0 = (st + y0c * Wl) * DHEAD;
            const int r1 = (st + y1c * Wl) * DHEAD;
            s_idx[u][pt][0] = r0 + x0c * DHEAD;
            s_idx[u][pt][1] = r0 + x1c * DHEAD;
            s_idx[u][pt][2] = r1 + x0c * DHEAD;
            s_idx[u][pt][3] = r1 + x1c * DHEAD;

            s_w[u][pt][0] = aw * (1.f - lx) * (1.f - ly) * vx0 * vy0;
            s_w[u][pt][1] = aw * lx * (1.f - ly) * vx1 * vy0;
            s_w[u][pt][2] = aw * (1.f - lx) * ly * vx0 * vy1;
            s_w[u][pt][3] = aw * lx * ly * vx1 * vy1;

            if (pt == 0) {
                const int n = mq / Lq;
                s_vbase[u] = ((n * NH + h) * Lq) * DHEAD;
            }
        }
    }
    __syncthreads();

    // ---------------- Phase 2 ----------------
    {
        const int warp = tid >> 5;
        const int lane = tid & 31;
#pragma unroll
        for (int uu = 0; uu < 2; uu++) {
            const int u  = warp * 2 + uu;
            const int gu = blockIdx.x * 16 + u;
            if (gu >= total) continue;

            const float* bp = g_value + s_vbase[u] + lane;
            float acc = 0.f;
#pragma unroll
            for (int pt = 0; pt < 16; pt++) {
                const int4   id = *reinterpret_cast<const int4*>(s_idx[u][pt]);
                const float4 w  = *reinterpret_cast<const float4*>(s_w[u][pt]);
                acc = fmaf(w.x, __ldg(bp + id.x), acc);
                acc = fmaf(w.y, __ldg(bp + id.y), acc);
                acc = fmaf(w.z, __ldg(bp + id.z), acc);
                acc = fmaf(w.w, __ldg(bp + id.w), acc);
            }
            g_acc[(size_t)gu * DHEAD + lane] = acc;
        }
    }
}

// ---------------------------------------------------------------------------
// Launch
// ---------------------------------------------------------------------------
extern "C" void kernel_launch(void* const* d_in, const int* in_sizes, int n_in,
                              void* d_out, int out_size)
{
    const float* query  = (const float*)d_in[0];
    const float* refp   = (const float*)d_in[1];
    const float* xin    = (const float*)d_in[2];
    const int*   shapes = (const int*)  d_in[3];
    const int*   lstart = (const int*)  d_in[4];
    const float* W_samp = (const float*)d_in[5];
    const float* b_samp = (const float*)d_in[6];
    const float* W_attn = (const float*)d_in[7];
    const float* b_attn = (const float*)d_in[8];
    const float* W_val  = (const float*)d_in[9];
    const float* b_val  = (const float*)d_in[10];
    const float* W_out  = (const float*)d_in[11];
    const float* b_out  = (const float*)d_in[12];
    float* out = (float*)d_out;

    const int Lq = in_sizes[0] / (BATCH * D_MODEL);
    const int M  = BATCH * Lq;

    void *pv, *po, *pa, *pc, *pwqk, *pbqk;
    cudaGetSymbolAddress(&pv, g_value);
    cudaGetSymbolAddress(&po, g_off);
    cudaGetSymbolAddress(&pa, g_attn);
    cudaGetSymbolAddress(&pc, g_acc);
    cudaGetSymbolAddress(&pwqk, g_Wqk);
    cudaGetSymbolAddress(&pbqk, g_bqk);

    const int gx = (M + BM - 1) / BM;
    dim3 blk(256);

    // 0) pack merged qk weights
    pack_qk<<<384, blk>>>(W_samp, b_samp, W_attn, b_attn);
    // 1) value projection (+ layout remap to (N,H,Lv,Dh))
    hgemm_nt<1><<<dim3(gx, 2), blk>>>(xin, W_val, b_val, (float*)pv, nullptr, M, Lq);
    // 2+3) merged sampling-offset + attention-logit projection (N = 384)
    hgemm_nt<2><<<dim3(gx, 3), blk>>>(query, (const float*)pwqk, (const float*)pbqk,
                                      (float*)po, (float*)pa, M, Lq);
    // 4) softmax + deformable sampling
    {
        const int total = M * NH;
        const int nblk  = (total + 15) / 16;
        msda_sample<<<nblk, blk>>>(refp, shapes, lstart, Lq, total);
    }
    // 5) output projection
    hgemm_nt<0><<<dim3(gx, 2), blk>>>((const float*)pc, W_out, b_out, out, nullptr, M, Lq);
}

// round 7
// speedup vs baseline: 1.5426x; 1.1156x over previous
#include <cuda_runtime.h>
#include <cuda_fp16.h>
#include <math.h>
#include <stdint.h>

#define D_MODEL 256
#define NH 8
#define NL 4
#define NP 4
#define DHEAD 32
#define BATCH 2
#define MAX_M 40960   // >= BATCH * Lq = 39894

// Scratch (static device globals -- no allocation at runtime)
__device__ __half g_valh[(size_t)MAX_M * D_MODEL];   // value, fp16 (N,H,Lv,Dh)
__device__ float  g_off [(size_t)MAX_M * D_MODEL];   // (N,Lq,H,L,P,2)
__device__ float  g_attn[(size_t)MAX_M * (NH*NL*NP)];// logits (N,Lq,H,16)
__device__ float  g_acc [(size_t)MAX_M * D_MODEL];   // (N,Lq,H,Dh)
__device__ float  g_Wqk [384 * 256];                 // W_samp ++ W_attn
__device__ float  g_bqk [384];

// ---------------------------------------------------------------------------
// FP16 mma.sync GEMM (fp32 accum): C[M,Ncols] = A[M,256] @ W[Ncols,256]^T + b
// CTA tile 128x128, 8 warps x (64x32) warp tile, m16n8k16, double-buffered.
// EPI 0: row-major f32 (stride 256). EPI 1: value remap -> fp16. EPI 2: split.
// ---------------------------------------------------------------------------
#define BM 128
#define BN 128
#define BKK 32
#define PADH 8

__device__ __forceinline__ void mma_f16(float* c, const uint32_t* a, const uint32_t* b) {
    asm volatile(
        "mma.sync.aligned.m16n8k16.row.col.f32.f16.f16.f32 "
        "{%0,%1,%2,%3}, {%4,%5,%6,%7}, {%8,%9}, {%0,%1,%2,%3};"
        : "+f"(c[0]), "+f"(c[1]), "+f"(c[2]), "+f"(c[3])
        : "r"(a[0]), "r"(a[1]), "r"(a[2]), "r"(a[3]), "r"(b[0]), "r"(b[1]));
}

template<int EPI>
__global__ __launch_bounds__(256)
void hgemm_nt(const float* __restrict__ A, const float* __restrict__ W,
              const float* __restrict__ bias, float* __restrict__ C0,
              float* __restrict__ C1, __half* __restrict__ CH, int M, int Lv)
{
    __shared__ alignas(16) __half As[2][BM][BKK + PADH];
    __shared__ alignas(16) __half Bs[2][BN][BKK + PADH];

    const int tid  = threadIdx.x;
    const int brow = blockIdx.x * BM;
    const int bcol = blockIdx.y * BN;
    const int K = 256;

    const int warp = tid >> 5;
    const int lane = tid & 31;
    const int wm   = (warp & 1) * 64;     // warp M offset
    const int wn   = (warp >> 1) * 32;    // warp N offset
    const int lr   = lane >> 2;           // 0..7
    const int lc   = lane & 3;            // 0..3

    const int ldRow = tid >> 1;           // 0..127
    const int ldSeg = (tid & 1) * 16;     // 0 or 16 (floats)
    const int grA   = brow + ldRow;
    const int grW   = bcol + ldRow;

    float4 pa[4], pw[4];

    // prefetch tile 0
#pragma unroll
    for (int j = 0; j < 4; j++) {
        pa[j] = (grA < M) ? *reinterpret_cast<const float4*>(A + (size_t)grA * K + ldSeg + j * 4)
                          : make_float4(0.f, 0.f, 0.f, 0.f);
        pw[j] = *reinterpret_cast<const float4*>(W + (size_t)grW * K + ldSeg + j * 4);
    }
#pragma unroll
    for (int j = 0; j < 4; j++) {
        *reinterpret_cast<__half2*>(&As[0][ldRow][ldSeg + j * 4    ]) = __float22half2_rn(make_float2(pa[j].x, pa[j].y));
        *reinterpret_cast<__half2*>(&As[0][ldRow][ldSeg + j * 4 + 2]) = __float22half2_rn(make_float2(pa[j].z, pa[j].w));
        *reinterpret_cast<__half2*>(&Bs[0][ldRow][ldSeg + j * 4    ]) = __float22half2_rn(make_float2(pw[j].x, pw[j].y));
        *reinterpret_cast<__half2*>(&Bs[0][ldRow][ldSeg + j * 4 + 2]) = __float22half2_rn(make_float2(pw[j].z, pw[j].w));
    }
    __syncthreads();

    float acc[4][4][4];
#pragma unroll
    for (int mt = 0; mt < 4; mt++)
#pragma unroll
        for (int nt = 0; nt < 4; nt++)
#pragma unroll
            for (int r = 0; r < 4; r++) acc[mt][nt][r] = 0.f;

    const int nk = K / BKK;               // 8
    for (int t = 0; t < nk; t++) {
        const int cur = t & 1;
        if (t + 1 < nk) {
            const int kt = (t + 1) * BKK;
#pragma unroll
            for (int j = 0; j < 4; j++) {
                pa[j] = (grA < M) ? *reinterpret_cast<const float4*>(A + (size_t)grA * K + kt + ldSeg + j * 4)
                                  : make_float4(0.f, 0.f, 0.f, 0.f);
                pw[j] = *reinterpret_cast<const float4*>(W + (size_t)grW * K + kt + ldSeg + j * 4);
            }
        }

#pragma unroll
        for (int ks = 0; ks < 2; ks++) {
            const int kb = ks * 16;
            uint32_t af[4][4], bf[4][2];
#pragma unroll
            for (int mt = 0; mt < 4; mt++) {
                const int m0 = wm + mt * 16;
                af[mt][0] = *reinterpret_cast<const uint32_t*>(&As[cur][m0 + lr    ][kb + lc * 2    ]);
                af[mt][1] = *reinterpret_cast<const uint32_t*>(&As[cur][m0 + lr + 8][kb + lc * 2    ]);
                af[mt][2] = *reinterpret_cast<const uint32_t*>(&As[cur][m0 + lr    ][kb + lc * 2 + 8]);
                af[mt][3] = *reinterpret_cast<const uint32_t*>(&As[cur][m0 + lr + 8][kb + lc * 2 + 8]);
            }
#pragma unroll
            for (int nt = 0; nt < 4; nt++) {
                const int n0 = wn + nt * 8;
                bf[nt][0] = *reinterpret_cast<const uint32_t*>(&Bs[cur][n0 + lr][kb + lc * 2    ]);
                bf[nt][1] = *reinterpret_cast<const uint32_t*>(&Bs[cur][n0 + lr][kb + lc * 2 + 8]);
            }
#pragma unroll
            for (int mt = 0; mt < 4; mt++)
#pragma unroll
                for (int nt = 0; nt < 4; nt++)
                    mma_f16(acc[mt][nt], af[mt], bf[nt]);
        }

        if (t + 1 < nk) {
            const int nxt = cur ^ 1;
#pragma unroll
            for (int j = 0; j < 4; j++) {
                *reinterpret_cast<__half2*>(&As[nxt][ldRow][ldSeg + j * 4    ]) = __float22half2_rn(make_float2(pa[j].x, pa[j].y));
                *reinterpret_cast<__half2*>(&As[nxt][ldRow][ldSeg + j * 4 + 2]) = __float22half2_rn(make_float2(pa[j].z, pa[j].w));
                *reinterpret_cast<__half2*>(&Bs[nxt][ldRow][ldSeg + j * 4    ]) = __float22half2_rn(make_float2(pw[j].x, pw[j].y));
                *reinterpret_cast<__half2*>(&Bs[nxt][ldRow][ldSeg + j * 4 + 2]) = __float22half2_rn(make_float2(pw[j].z, pw[j].w));
            }
        }
        __syncthreads();
    }

    // Epilogue: mma tile rows {lr, lr+8}, cols {2*lc, 2*lc+1}
#pragma unroll
    for (int mt = 0; mt < 4; mt++) {
#pragma unroll
        for (int nt = 0; nt < 4; nt++) {
            const int c0 = bcol + wn + nt * 8 + lc * 2;
            const float b0 = __ldg(bias + c0);
            const float b1 = __ldg(bias + c0 + 1);
#pragma unroll
            for (int rr = 0; rr < 2; rr++) {
                const int r = brow + wm + mt * 16 + lr + rr * 8;
                if (r >= M) continue;
                const float v0 = acc[mt][nt][rr * 2 + 0] + b0;
                const float v1 = acc[mt][nt][rr * 2 + 1] + b1;
                if (EPI == 0) {
                    *reinterpret_cast<float2*>(C0 + (size_t)r * 256 + c0) = make_float2(v0, v1);
                } else if (EPI == 1) {
                    const int nb = r / Lv, l = r - nb * Lv;
                    const int h = c0 >> 5, dh = c0 & 31;  // c0 even -> pair stays in one head
                    __half* p = CH + ((((size_t)(nb * NH + h)) * Lv) + l) * DHEAD + dh;
                    *reinterpret_cast<__half2*>(p) = __float22half2_rn(make_float2(v0, v1));
                } else {
                    if (c0 < 256)
                        *reinterpret_cast<float2*>(C0 + (size_t)r * 256 + c0) = make_float2(v0, v1);
                    else
                        *reinterpret_cast<float2*>(C1 + (size_t)r * 128 + (c0 - 256)) = make_float2(v0, v1);
                }
            }
        }
    }
}

// ---------------------------------------------------------------------------
// Pack W_samp ++ W_attn into one 384x256 weight (shared-A GEMM merge)
// ---------------------------------------------------------------------------
__global__ void pack_qk(const float* __restrict__ Ws, const float* __restrict__ bs,
                        const float* __restrict__ Wa, const float* __restrict__ ba)
{
    const int i = blockIdx.x * 256 + threadIdx.x;
    if (i < 65536)       g_Wqk[i] = Ws[i];
    else if (i < 98304)  g_Wqk[i] = Wa[i - 65536];
    if (i < 256)         g_bqk[i] = bs[i];
    else if (i < 384)    g_bqk[i] = ba[i - 256];
}

// ---------------------------------------------------------------------------
// Sampling + softmax, two-phase.
// Phase 1: thread (u,pt) computes softmax weight + 4 corner offsets/weights,
//          stored in corner order [x0y0, x0y1, x1y0, x1y1] (pairs per x-corner).
// Phase 2: lane = (x-corner half, channel pair); one LDG covers 2 corners via
//          half2 values; shfl_xor(16) combines; 32 LDG/unit instead of 64.
// ---------------------------------------------------------------------------
__global__ __launch_bounds__(256)
void msda_sample(const float* __restrict__ ref,
                 const int* __restrict__ shapes,
                 const int* __restrict__ lstart,
                 int Lq, int total)
{
    __shared__ int   s_idx[16][16][4];
    __shared__ float s_w  [16][16][4];
    __shared__ int   s_vbase[16];

    const int tid = threadIdx.x;

    // ---------------- Phase 1 ----------------
    {
        const int u  = tid >> 4;
        const int pt = tid & 15;
        const int gu = blockIdx.x * 16 + u;
        const bool act = gu < total;

        const int h  = gu & (NH - 1);
        const int mq = gu >> 3;                    // n*Lq + q

        float logit = act ? __ldg(g_attn + (size_t)gu * 16 + pt) : 0.f;
        float mx = logit;
#pragma unroll
        for (int s = 8; s > 0; s >>= 1) mx = fmaxf(mx, __shfl_xor_sync(0xffffffffu, mx, s));
        float e = __expf(logit - mx);
        float sum = e;
#pragma unroll
        for (int s = 8; s > 0; s >>= 1) sum += __shfl_xor_sync(0xffffffffu, sum, s);
        const float aw = e / sum;

        if (act) {
            const int lvl = pt >> 2;
            const int Hl = __ldg(shapes + lvl * 2 + 0);
            const int Wl = __ldg(shapes + lvl * 2 + 1);
            const int st = __ldg(lstart + lvl);

            const float rx = __ldg(ref + (size_t)mq * (NL * 2) + lvl * 2 + 0);
            const float ry = __ldg(ref + (size_t)mq * (NL * 2) + lvl * 2 + 1);
            const float ox = __ldg(g_off + (size_t)gu * 32 + 2 * pt + 0);
            const float oy = __ldg(g_off + (size_t)gu * 32 + 2 * pt + 1);

            const float x = fmaf(rx, (float)Wl, ox) - 0.5f;
            const float y = fmaf(ry, (float)Hl, oy) - 0.5f;
            const float xf = floorf(x), yf = floorf(y);
            const float lx = x - xf, ly = y - yf;
            const int x0 = (int)xf, y0 = (int)yf;
            const int x1 = x0 + 1,  y1 = y0 + 1;

            const float vx0 = (x0 >= 0 && x0 < Wl) ? 1.f : 0.f;
            const float vx1 = (x1 >= 0 && x1 < Wl) ? 1.f : 0.f;
            const float vy0 = (y0 >= 0 && y0 < Hl) ? 1.f : 0.f;
            const float vy1 = (y1 >= 0 && y1 < Hl) ? 1.f : 0.f;

            const int x0c = min(max(x0, 0), Wl - 1);
            const int x1c = min(max(x1, 0), Wl - 1);
            const int y0c = min(max(y0, 0), Hl - 1);
            const int y1c = min(max(y1, 0), Hl - 1);

            const int r0 = (st + y0c * Wl) * DHEAD;
            const int r1 = (st + y1c * Wl) * DHEAD;
            // corner order: [x0y0, x0y1, x1y0, x1y1]
            s_idx[u][pt][0] = r0 + x0c * DHEAD;
            s_idx[u][pt][1] = r1 + x0c * DHEAD;
            s_idx[u][pt][2] = r0 + x1c * DHEAD;
            s_idx[u][pt][3] = r1 + x1c * DHEAD;

            s_w[u][pt][0] = aw * (1.f - lx) * (1.f - ly) * vx0 * vy0;
            s_w[u][pt][1] = aw * (1.f - lx) * ly * vx0 * vy1;
            s_w[u][pt][2] = aw * lx * (1.f - ly) * vx1 * vy0;
            s_w[u][pt][3] = aw * lx * ly * vx1 * vy1;

            if (pt == 0) {
                const int n = mq / Lq;
                s_vbase[u] = ((n * NH + h) * Lq) * DHEAD;
            }
        }
    }
    __syncthreads();

    // ---------------- Phase 2 ----------------
    {
        const int warp   = tid >> 5;
        const int lane   = tid & 31;
        const int corner = lane >> 4;     // 0: x0 pair, 1: x1 pair
        const int cp     = lane & 15;     // channel pair index
#pragma unroll
        for (int uu = 0; uu < 2; uu++) {
            const int u  = warp * 2 + uu;
            const int gu = blockIdx.x * 16 + u;
            if (gu >= total) continue;

            const __half* bp = g_valh + s_vbase[u] + cp * 2;
            float ax = 0.f, ay = 0.f;
#pragma unroll
            for (int pt = 0; pt < 16; pt++) {
                const int2   id = *reinterpret_cast<const int2*>(&s_idx[u][pt][corner * 2]);
                const float2 w  = *reinterpret_cast<const float2*>(&s_w[u][pt][corner * 2]);
                const float2 va = __half22float2(*reinterpret_cast<const __half2*>(bp + id.x));
                const float2 vb = __half22float2(*reinterpret_cast<const __half2*>(bp + id.y));
                ax = fmaf(w.x, va.x, fmaf(w.y, vb.x, ax));
                ay = fmaf(w.x, va.y, fmaf(w.y, vb.y, ay));
            }
            ax += __shfl_xor_sync(0xffffffffu, ax, 16);
            ay += __shfl_xor_sync(0xffffffffu, ay, 16);
            if (corner == 0)
                *reinterpret_cast<float2*>(g_acc + (size_t)gu * DHEAD + cp * 2) = make_float2(ax, ay);
        }
    }
}

// ---------------------------------------------------------------------------
// Launch
// ---------------------------------------------------------------------------
extern "C" void kernel_launch(void* const* d_in, const int* in_sizes, int n_in,
                              void* d_out, int out_size)
{
    const float* query  = (const float*)d_in[0];
    const float* refp   = (const float*)d_in[1];
    const float* xin    = (const float*)d_in[2];
    const int*   shapes = (const int*)  d_in[3];
    const int*   lstart = (const int*)  d_in[4];
    const float* W_samp = (const float*)d_in[5];
    const float* b_samp = (const float*)d_in[6];
    const float* W_attn = (const float*)d_in[7];
    const float* b_attn = (const float*)d_in[8];
    const float* W_val  = (const float*)d_in[9];
    const float* b_val  = (const float*)d_in[10];
    const float* W_out  = (const float*)d_in[11];
    const float* b_out  = (const float*)d_in[12];
    float* out = (float*)d_out;

    const int Lq = in_sizes[0] / (BATCH * D_MODEL);
    const int M  = BATCH * Lq;

    void *pvh, *po, *pa, *pc, *pwqk, *pbqk;
    cudaGetSymbolAddress(&pvh, g_valh);
    cudaGetSymbolAddress(&po, g_off);
    cudaGetSymbolAddress(&pa, g_attn);
    cudaGetSymbolAddress(&pc, g_acc);
    cudaGetSymbolAddress(&pwqk, g_Wqk);
    cudaGetSymbolAddress(&pbqk, g_bqk);

    const int gx = (M + BM - 1) / BM;
    dim3 blk(256);

    // 0) pack merged qk weights
    pack_qk<<<384, blk>>>(W_samp, b_samp, W_attn, b_attn);
    // 1) value projection (+ layout remap to (N,H,Lv,Dh), fp16 out)
    hgemm_nt<1><<<dim3(gx, 2), blk>>>(xin, W_val, b_val, nullptr, nullptr, (__half*)pvh, M, Lq);
    // 2+3) merged sampling-offset + attention-logit projection (N = 384)
    hgemm_nt<2><<<dim3(gx, 3), blk>>>(query, (const float*)pwqk, (const float*)pbqk,
                                      (float*)po, (float*)pa, nullptr, M, Lq);
    // 4) softmax + deformable sampling
    {
        const int total = M * NH;
        const int nblk  = (total + 15) / 16;
        msda_sample<<<nblk, blk>>>(refp, shapes, lstart, Lq, total);
    }
    // 5) output projection
    hgemm_nt<0><<<dim3(gx, 2), blk>>>((const float*)pc, W_out, b_out, out, nullptr, nullptr, M, Lq);
}